// round 4
// baseline (speedup 1.0000x reference)
#include <cuda_runtime.h>
#include <cstdint>

// ---------------------------------------------------------------------------
// Problem shape
// ---------------------------------------------------------------------------
#define M_ 16384           // B*S token rows
#define P_ 512             // prototypes (= N)
#define D_ 768             // feature dim (= K)
#define BM 128
#define BN 128
#define BKF 32             // K floats per stage
#define NS (D_ / BKF)      // 24 stages
#define NTH 256

// smem offsets (relative to 1024-aligned base)
// A: [128 rows][36 floats] padded for ldmatrix bank spread: 128*144 = 18432 B
// B: fragment-ordered: 64 regions (kg 0..3 x nt 0..15) x 256 B = 16384 B
#define OFF_A0 0
#define OFF_A1 18432
#define OFF_B0 36864
#define OFF_B1 53248
#define OFF_SXS 69632      // 128 floats
#define OFF_SPS 70144      // 128 floats
#define OFF_SPART 70656    // 512 floats
#define SMEM_BYTES (72704 + 1024)

__device__ __forceinline__ void cp_async16(uint32_t d, const void* s) {
    asm volatile("cp.async.cg.shared.global [%0], [%1], 16;" ::"r"(d), "l"(s));
}
#define CP_COMMIT() asm volatile("cp.async.commit_group;" ::: "memory")
#define CP_WAIT1()  asm volatile("cp.async.wait_group 1;" ::: "memory")
#define CP_WAIT0()  asm volatile("cp.async.wait_group 0;" ::: "memory")

#define LDSM_X4(r0, r1, r2, r3, a)                                             \
    asm volatile("ldmatrix.sync.aligned.m8n8.x4.shared.b16 {%0,%1,%2,%3}, [%4];" \
                 : "=r"(r0), "=r"(r1), "=r"(r2), "=r"(r3) : "r"(a))

#define MMA_TF32(c0, c1, c2, c3, a0, a1, a2, a3, b0, b1)                       \
    asm volatile("mma.sync.aligned.m16n8k8.row.col.f32.tf32.tf32.f32 "         \
                 "{%0,%1,%2,%3}, {%4,%5,%6,%7}, {%8,%9}, {%0,%1,%2,%3};"       \
                 : "+f"(c0), "+f"(c1), "+f"(c2), "+f"(c3)                      \
                 : "r"(a0), "r"(a1), "r"(a2), "r"(a3), "r"(b0), "r"(b1))

// ---------------------------------------------------------------------------
__global__ __launch_bounds__(NTH, 2)
void dist_tf32_v2_kernel(const float* __restrict__ A,
                         const float* __restrict__ Bp,
                         float* __restrict__ C) {
    extern __shared__ char smem_dyn[];
    uint32_t sb0;
    asm("{ .reg .u64 t; cvta.to.shared.u64 t, %1; cvt.u32.u64 %0, t; }"
        : "=r"(sb0) : "l"(smem_dyn));
    const uint32_t pad = (1024u - (sb0 & 1023u)) & 1023u;
    const uint32_t sb = sb0 + pad;
    char* sbase = smem_dyn + pad;

    const int tid  = threadIdx.x;
    const int lane = tid & 31;
    const int warp = tid >> 5;
    const int wm   = warp & 3;      // warp tile: 32 rows
    const int wn   = warp >> 2;     // warp tile: 64 cols
    const int g    = lane >> 2;
    const int t    = lane & 3;
    const int bx   = blockIdx.x;    // N tile (0..3)
    const int by   = blockIdx.y;    // M tile (0..127)

    const float* Ablk = A  + (size_t)by * BM * D_;
    const float* Bblk = Bp + (size_t)bx * BN * D_;

    // ldmatrix per-lane address components (A layout: [row][36 floats])
    const uint32_t lm_off = (uint32_t)(((wm * 32 + (lane & 15)) * 36 + (lane >> 4) * 4) * 4);

    // B loader units: u0 = tid, u1 = tid + 256;  n = u>>2, kg = u&3
    const int n0 = tid >> 2,  kg0 = tid & 3;
    const int n1 = (tid + 256) >> 2, kg1 = (tid + 256) & 3;
    // fragment-order STS base: region (kg*16 + n/8)*256 + (n%8)*4*8
    const uint32_t bsts0 = (uint32_t)((kg0 * 16 + (n0 >> 3)) * 256 + (n0 & 7) * 32);
    const uint32_t bsts1 = (uint32_t)((kg1 * 16 + (n1 >> 3)) * 256 + (n1 & 7) * 32);

    float4 bq[2][2];                 // B staging regs (one stage lookahead)
    float pq0 = 0.f, pq1 = 0.f;      // psq partials per unit
    float xs[4] = {0.f, 0.f, 0.f, 0.f};
    float c[2][8][4];
    #pragma unroll
    for (int i = 0; i < 2; i++)
        #pragma unroll
        for (int j = 0; j < 8; j++)
            #pragma unroll
            for (int q = 0; q < 4; q++) c[i][j][q] = 0.f;

    auto ldgB = [&](int s) {
        const int kf = s * BKF;
        const float* s0 = Bblk + (size_t)n0 * D_ + kf + kg0 * 8;
        const float* s1 = Bblk + (size_t)n1 * D_ + kf + kg1 * 8;
        bq[0][0] = *reinterpret_cast<const float4*>(s0);
        bq[0][1] = *reinterpret_cast<const float4*>(s0 + 4);
        bq[1][0] = *reinterpret_cast<const float4*>(s1);
        bq[1][1] = *reinterpret_cast<const float4*>(s1 + 4);
    };
    auto stsB = [&](int s) {         // also accumulates psq from staged regs
        const uint32_t bb = (s & 1) ? OFF_B1 : OFF_B0;
        const float* q0 = reinterpret_cast<const float*>(&bq[0][0]);
        const float* q1 = reinterpret_cast<const float*>(&bq[0][1]);
        const float* r0 = reinterpret_cast<const float*>(&bq[1][0]);
        const float* r1 = reinterpret_cast<const float*>(&bq[1][1]);
        #pragma unroll
        for (int t2 = 0; t2 < 4; t2++) {
            *reinterpret_cast<float2*>(sbase + bb + bsts0 + t2 * 8) =
                make_float2(q0[t2], q1[t2]);
            *reinterpret_cast<float2*>(sbase + bb + bsts1 + t2 * 8) =
                make_float2(r0[t2], r1[t2]);
            pq0 = fmaf(q0[t2], q0[t2], fmaf(q1[t2], q1[t2], pq0));
            pq1 = fmaf(r0[t2], r0[t2], fmaf(r1[t2], r1[t2], pq1));
        }
    };
    auto cpA = [&](int s) {
        const int kf = s * BKF;
        const uint32_t ab = sb + ((s & 1) ? OFF_A1 : OFF_A0);
        #pragma unroll
        for (int j = 0; j < 4; j++) {
            const int u = tid + j * 256;
            const int row = u >> 3, uc = u & 7;
            cp_async16(ab + (uint32_t)(row * 144 + uc * 16),
                       Ablk + (size_t)row * D_ + kf + uc * 4);
        }
    };

    // ---- prologue ----
    ldgB(0);
    cpA(0); CP_COMMIT();
    stsB(0);
    ldgB(1);
    cpA(1); CP_COMMIT();
    CP_WAIT1();
    __syncthreads();

    // ---- mainloop ----
    for (int s = 0; s < NS; ++s) {
        const int buf = s & 1;
        if (s + 1 < NS) stsB(s + 1);          // into buf^1 (free since last sync)
        if (s + 2 < NS) ldgB(s + 2);

        const uint32_t a_sb = sb + (buf ? OFF_A1 : OFF_A0);
        const char* bbp = sbase + (buf ? OFF_B1 : OFF_B0);

        #pragma unroll
        for (int kg = 0; kg < 4; kg++) {
            uint32_t af[2][4];
            #pragma unroll
            for (int i = 0; i < 2; i++) {
                const uint32_t addr = a_sb + lm_off + (uint32_t)(i * 16 * 144 + kg * 32);
                LDSM_X4(af[i][0], af[i][1], af[i][2], af[i][3], addr);
                if (wn == 0) {       // fused ||x||^2 on raw f32 bits
                    const float a0 = __uint_as_float(af[i][0]);
                    const float a1 = __uint_as_float(af[i][1]);
                    const float a2 = __uint_as_float(af[i][2]);
                    const float a3 = __uint_as_float(af[i][3]);
                    xs[i * 2 + 0] = fmaf(a0, a0, fmaf(a2, a2, xs[i * 2 + 0]));
                    xs[i * 2 + 1] = fmaf(a1, a1, fmaf(a3, a3, xs[i * 2 + 1]));
                }
            }
            #pragma unroll
            for (int j = 0; j < 8; j++) {
                const float2 b = *reinterpret_cast<const float2*>(
                    bbp + ((kg * 16 + wn * 8 + j) << 8) + (lane << 3));
                const uint32_t ub0 = __float_as_uint(b.x);
                const uint32_t ub1 = __float_as_uint(b.y);
                #pragma unroll
                for (int i = 0; i < 2; i++)
                    MMA_TF32(c[i][j][0], c[i][j][1], c[i][j][2], c[i][j][3],
                             af[i][0], af[i][1], af[i][2], af[i][3], ub0, ub1);
            }
        }

        __syncthreads();                      // buf consumed; STS(s+1) visible
        if (s + 2 < NS) { cpA(s + 2); CP_COMMIT(); CP_WAIT1(); }
        else if (s + 1 < NS) { CP_WAIT0(); }
        __syncthreads();                      // A(s+1) visible to all
    }

    // ---- norms: publish partials, reduce ----
    float* sxs = reinterpret_cast<float*>(sbase + OFF_SXS);
    float* sps = reinterpret_cast<float*>(sbase + OFF_SPS);
    float* spp = reinterpret_cast<float*>(sbase + OFF_SPART);
    spp[tid] = pq0;
    spp[tid + 256] = pq1;
    if (wn == 0) {
        #pragma unroll
        for (int q = 0; q < 4; q++) {
            xs[q] += __shfl_xor_sync(0xffffffffu, xs[q], 1);
            xs[q] += __shfl_xor_sync(0xffffffffu, xs[q], 2);
        }
        if (t == 0) {
            sxs[wm * 32 + g     ] = xs[0];
            sxs[wm * 32 + g + 8 ] = xs[1];
            sxs[wm * 32 + g + 16] = xs[2];
            sxs[wm * 32 + g + 24] = xs[3];
        }
    }
    __syncthreads();
    if (tid < 128) {
        sps[tid] = spp[tid * 4] + spp[tid * 4 + 1] + spp[tid * 4 + 2] + spp[tid * 4 + 3];
    }
    __syncthreads();

    // ---- epilogue: dist = xs + ps - 2*cross ----
    #pragma unroll
    for (int i = 0; i < 2; i++) {
        const int ml = wm * 32 + i * 16 + g;
        const float x0 = sxs[ml];
        const float x1 = sxs[ml + 8];
        const int mg = by * BM + ml;
        float* row0 = C + (size_t)mg * P_;
        float* row1 = C + (size_t)(mg + 8) * P_;
        #pragma unroll
        for (int j = 0; j < 8; j++) {
            const int nl = wn * 64 + j * 8 + 2 * t;
            const float p0 = sps[nl];
            const float p1 = sps[nl + 1];
            const int ng = bx * BN + nl;
            float2 v0, v1;
            v0.x = x0 + p0 - 2.f * c[i][j][0];
            v0.y = x0 + p1 - 2.f * c[i][j][1];
            v1.x = x1 + p0 - 2.f * c[i][j][2];
            v1.y = x1 + p1 - 2.f * c[i][j][3];
            *reinterpret_cast<float2*>(row0 + ng) = v0;
            *reinterpret_cast<float2*>(row1 + ng) = v1;
        }
    }
}

// ---------------------------------------------------------------------------
extern "C" void kernel_launch(void* const* d_in, const int* in_sizes, int n_in,
                              void* d_out, int out_size) {
    const float* inputs = (const float*)d_in[0];   // [M_, D_]
    const float* protos = (const float*)d_in[1];   // [P_, D_]
    float* out = (float*)d_out;

    cudaFuncSetAttribute(dist_tf32_v2_kernel,
                         cudaFuncAttributeMaxDynamicSharedMemorySize, SMEM_BYTES);
    dim3 grid(P_ / BN, M_ / BM);   // (4, 128)
    dist_tf32_v2_kernel<<<grid, NTH, SMEM_BYTES>>>(inputs, protos, out);

    // Second tuple output: prototypes passed through unchanged.
    cudaMemcpyAsync(out + (size_t)M_ * P_, protos,
                    (size_t)P_ * D_ * sizeof(float),
                    cudaMemcpyDeviceToDevice);
}

// round 5
// speedup vs baseline: 1.5189x; 1.5189x over previous
#include <cuda_runtime.h>
#include <cuda_fp16.h>
#include <cstdint>

// ---------------------------------------------------------------------------
#define M_ 16384           // B*S token rows
#define P_ 512             // prototypes (= N)
#define D_ 768             // feature dim (= K)
#define BM 128
#define BN 128
#define BKF 64             // K floats per stage
#define NS (D_ / BKF)      // 12 stages
#define NTH 256
#define RSH 72             // smem row stride in halves (64 + 8 pad)
#define ABUF (128 * RSH * 2)   // 18432 bytes per buffer
#define SMEM_BYTES (4 * ABUF + 1024)

__device__ float g_xsq[M_];
__device__ float g_psq[P_];

// ---------------------------------------------------------------------------
// Norm kernel: block = 256 thr handles 16 rows; thread (r=tid>>4, kq=tid&15)
// reads 12 coalesced float4 (full row across 16 lanes), shfl-reduce.
// ---------------------------------------------------------------------------
__global__ void norms_kernel(const float* __restrict__ X,
                             const float* __restrict__ Pp) {
    const int r  = threadIdx.x >> 4;
    const int kq = threadIdx.x & 15;
    const int row = blockIdx.x * 16 + r;
    const float* src;
    float* dst;
    if (row < M_) { src = X + (size_t)row * D_;         dst = g_xsq + row; }
    else          { src = Pp + (size_t)(row - M_) * D_; dst = g_psq + (row - M_); }
    float s = 0.f;
    #pragma unroll
    for (int i = 0; i < 12; i++) {          // k = i*64 + kq*4
        float4 v = *reinterpret_cast<const float4*>(src + i * 64 + kq * 4);
        s += v.x * v.x + v.y * v.y + v.z * v.z + v.w * v.w;
    }
    #pragma unroll
    for (int o = 8; o; o >>= 1) s += __shfl_xor_sync(0xffffffffu, s, o);
    if (kq == 0) *dst = s;
}

// ---------------------------------------------------------------------------
__device__ __forceinline__ uint32_t pack2(float x, float y) {
    __half2 h = __floats2half2_rn(x, y);
    return *reinterpret_cast<uint32_t*>(&h);
}

#define MMA_F16(c0, c1, c2, c3, a0, a1, a2, a3, b0, b1)                        \
    asm volatile("mma.sync.aligned.m16n8k16.row.col.f32.f16.f16.f32 "          \
                 "{%0,%1,%2,%3}, {%4,%5,%6,%7}, {%8,%9}, {%0,%1,%2,%3};"       \
                 : "+f"(c0), "+f"(c1), "+f"(c2), "+f"(c3)                      \
                 : "r"(a0), "r"(a1), "r"(a2), "r"(a3), "r"(b0), "r"(b1))

// ---------------------------------------------------------------------------
// Fused distance GEMM, fp16 tensor cores:
//   C[m][n] = xsq[m] + psq[n] - 2 * sum_k A[m][k] * B[n][k]
// 256 threads, 8 warps (4 wm x 2 wn), warp tile 32 x 64.
// ---------------------------------------------------------------------------
__global__ __launch_bounds__(NTH, 2)
void dist_f16_kernel(const float* __restrict__ A,
                     const float* __restrict__ Bp,
                     float* __restrict__ C) {
    extern __shared__ __align__(16) char smem[];
    __half* const sA[2] = { reinterpret_cast<__half*>(smem),
                            reinterpret_cast<__half*>(smem + ABUF) };
    __half* const sB[2] = { reinterpret_cast<__half*>(smem + 2 * ABUF),
                            reinterpret_cast<__half*>(smem + 3 * ABUF) };

    const int tid  = threadIdx.x;
    const int lane = tid & 31;
    const int warp = tid >> 5;
    const int wm   = warp & 3;       // 4 warps along M -> 32 rows
    const int wn   = warp >> 2;      // 2 warps along N -> 64 cols
    const int g    = lane >> 2;
    const int t    = lane & 3;
    const int bx   = blockIdx.x;     // N tile (0..3)
    const int by   = blockIdx.y;     // M tile (0..127)

    const float* Ablk = A  + (size_t)by * BM * D_;
    const float* Bblk = Bp + (size_t)bx * BN * D_;

    // loader mapping: idx = tid + 256*j (j=0..7): row = (tid>>4)+16j, kq = tid&15
    const int lr = tid >> 4;         // 0..15
    const int kq = tid & 15;

    uint32_t stA[16], stB[16];       // staged half2 (one stage lookahead)

    auto ldg_cvt = [&](int s) {
        const int kf = s * BKF + kq * 4;
        #pragma unroll
        for (int j = 0; j < 8; j++) {
            const int row = lr + 16 * j;
            float4 va = *reinterpret_cast<const float4*>(Ablk + (size_t)row * D_ + kf);
            float4 vb = *reinterpret_cast<const float4*>(Bblk + (size_t)row * D_ + kf);
            stA[2 * j]     = pack2(va.x, va.y);
            stA[2 * j + 1] = pack2(va.z, va.w);
            stB[2 * j]     = pack2(vb.x, vb.y);
            stB[2 * j + 1] = pack2(vb.z, vb.w);
        }
    };
    auto sts = [&](int s) {
        const int buf = s & 1;
        #pragma unroll
        for (int j = 0; j < 8; j++) {
            const int row = lr + 16 * j;
            *reinterpret_cast<uint2*>(sA[buf] + row * RSH + kq * 4) =
                make_uint2(stA[2 * j], stA[2 * j + 1]);
            *reinterpret_cast<uint2*>(sB[buf] + row * RSH + kq * 4) =
                make_uint2(stB[2 * j], stB[2 * j + 1]);
        }
    };

    float c[2][8][4];
    #pragma unroll
    for (int i = 0; i < 2; i++)
        #pragma unroll
        for (int j = 0; j < 8; j++)
            #pragma unroll
            for (int q = 0; q < 4; q++) c[i][j][q] = 0.f;

    // ---- prologue ----
    ldg_cvt(0);
    sts(0);
    ldg_cvt(1);
    __syncthreads();

    // ---- mainloop: one barrier per stage ----
    for (int s = 0; s < NS; ++s) {
        const int buf = s & 1;
        if (s + 1 < NS) sts(s + 1);          // into buf^1 (free after prev sync)
        if (s + 2 < NS) ldg_cvt(s + 2);      // refill staging regs

        const __half* Asb = sA[buf];
        const __half* Bsb = sB[buf];

        #pragma unroll
        for (int kk = 0; kk < 4; kk++) {     // 4 k16 chunks per stage
            const int kb = kk * 16 + 2 * t;
            uint32_t a[2][4];
            #pragma unroll
            for (int i = 0; i < 2; i++) {
                const int m0 = wm * 32 + i * 16;
                a[i][0] = *reinterpret_cast<const uint32_t*>(Asb + (m0 + g) * RSH + kb);
                a[i][1] = *reinterpret_cast<const uint32_t*>(Asb + (m0 + g + 8) * RSH + kb);
                a[i][2] = *reinterpret_cast<const uint32_t*>(Asb + (m0 + g) * RSH + kb + 8);
                a[i][3] = *reinterpret_cast<const uint32_t*>(Asb + (m0 + g + 8) * RSH + kb + 8);
            }
            #pragma unroll
            for (int j = 0; j < 8; j++) {
                const int n0 = wn * 64 + j * 8;
                const uint32_t b0 = *reinterpret_cast<const uint32_t*>(Bsb + (n0 + g) * RSH + kb);
                const uint32_t b1 = *reinterpret_cast<const uint32_t*>(Bsb + (n0 + g) * RSH + kb + 8);
                #pragma unroll
                for (int i = 0; i < 2; i++)
                    MMA_F16(c[i][j][0], c[i][j][1], c[i][j][2], c[i][j][3],
                            a[i][0], a[i][1], a[i][2], a[i][3], b0, b1);
            }
        }
        __syncthreads();
    }

    // ---- epilogue: dist = xsq + psq - 2*cross (norms from precomputed arrays)
    #pragma unroll
    for (int i = 0; i < 2; i++) {
        const int mg0 = by * BM + wm * 32 + i * 16 + g;
        const float x0 = g_xsq[mg0];
        const float x1 = g_xsq[mg0 + 8];
        float* row0 = C + (size_t)mg0 * P_;
        float* row1 = C + (size_t)(mg0 + 8) * P_;
        #pragma unroll
        for (int j = 0; j < 8; j++) {
            const int ng = bx * BN + wn * 64 + j * 8 + 2 * t;
            const float p0 = g_psq[ng];
            const float p1 = g_psq[ng + 1];
            float2 v0, v1;
            v0.x = x0 + p0 - 2.f * c[i][j][0];
            v0.y = x0 + p1 - 2.f * c[i][j][1];
            v1.x = x1 + p0 - 2.f * c[i][j][2];
            v1.y = x1 + p1 - 2.f * c[i][j][3];
            *reinterpret_cast<float2*>(row0 + ng) = v0;
            *reinterpret_cast<float2*>(row1 + ng) = v1;
        }
    }
}

// ---------------------------------------------------------------------------
extern "C" void kernel_launch(void* const* d_in, const int* in_sizes, int n_in,
                              void* d_out, int out_size) {
    const float* inputs = (const float*)d_in[0];   // [M_, D_]
    const float* protos = (const float*)d_in[1];   // [P_, D_]
    float* out = (float*)d_out;

    // 1) row norms (exact f32, matches reference)
    norms_kernel<<<(M_ + P_) / 16, 256>>>(inputs, protos);

    // 2) fused distance GEMM on fp16 tensor cores
    cudaFuncSetAttribute(dist_f16_kernel,
                         cudaFuncAttributeMaxDynamicSharedMemorySize, SMEM_BYTES);
    dim3 grid(P_ / BN, M_ / BM);   // (4, 128)
    dist_f16_kernel<<<grid, NTH, SMEM_BYTES>>>(inputs, protos, out);

    // 3) second tuple output: prototypes passed through unchanged
    cudaMemcpyAsync(out + (size_t)M_ * P_, protos,
                    (size_t)P_ * D_ * sizeof(float),
                    cudaMemcpyDeviceToDevice);
}

// round 6
// speedup vs baseline: 2.1598x; 1.4220x over previous
#include <cuda_runtime.h>
#include <cuda_fp16.h>
#include <cstdint>

// ---------------------------------------------------------------------------
#define M_ 16384           // B*S token rows
#define P_ 512             // prototypes (= N)
#define D_ 768             // feature dim (= K)
#define BM 128
#define BN 128
#define BKH 64             // K halves per stage (128 B per row)
#define NS (D_ / BKH)      // 12 stages
#define NTH 256
#define STAGES 3
#define TILEB 16384        // one operand tile: 128 rows x 128 B
#define STAGEB (2 * TILEB)
#define SMEM_BYTES (STAGES * STAGEB + 128)

__device__ __half g_a16[(size_t)M_ * D_];
__device__ __half g_b16[(size_t)P_ * D_];
__device__ float  g_xsq[M_];
__device__ float  g_psq[P_];

// ---------------------------------------------------------------------------
// Prep: one pass over f32 inputs -> fp16 copies + exact f32 row norms.
// Block = 256 thr = 16 rows x 16 lanes; each lane reads 12 float4.
// ---------------------------------------------------------------------------
__global__ void prep_kernel(const float* __restrict__ X,
                            const float* __restrict__ Pp) {
    const int r   = threadIdx.x >> 4;
    const int kq  = threadIdx.x & 15;
    const int row = blockIdx.x * 16 + r;
    const float* src;
    __half* dst16;
    float* dstn;
    if (row < M_) {
        src = X + (size_t)row * D_;  dst16 = g_a16 + (size_t)row * D_;  dstn = g_xsq + row;
    } else {
        const int pr = row - M_;
        src = Pp + (size_t)pr * D_;  dst16 = g_b16 + (size_t)pr * D_;   dstn = g_psq + pr;
    }
    float s = 0.f;
    #pragma unroll
    for (int i = 0; i < 12; i++) {
        float4 v = *reinterpret_cast<const float4*>(src + i * 64 + kq * 4);
        s = fmaf(v.x, v.x, fmaf(v.y, v.y, fmaf(v.z, v.z, fmaf(v.w, v.w, s))));
        __half2 h01 = __floats2half2_rn(v.x, v.y);
        __half2 h23 = __floats2half2_rn(v.z, v.w);
        *reinterpret_cast<uint2*>(dst16 + i * 64 + kq * 4) =
            make_uint2(*reinterpret_cast<uint32_t*>(&h01),
                       *reinterpret_cast<uint32_t*>(&h23));
    }
    #pragma unroll
    for (int o = 8; o; o >>= 1) s += __shfl_xor_sync(0xffffffffu, s, o);
    if (kq == 0) *dstn = s;
}

// ---------------------------------------------------------------------------
__device__ __forceinline__ void cp_async16(uint32_t d, const void* s) {
    asm volatile("cp.async.cg.shared.global [%0], [%1], 16;" ::"r"(d), "l"(s));
}
#define CP_COMMIT() asm volatile("cp.async.commit_group;" ::: "memory")
#define CP_WAIT_1() asm volatile("cp.async.wait_group 1;" ::: "memory")
#define CP_WAIT_0() asm volatile("cp.async.wait_group 0;" ::: "memory")

#define LDSM_X4(r0, r1, r2, r3, a)                                             \
    asm volatile("ldmatrix.sync.aligned.m8n8.x4.shared.b16 {%0,%1,%2,%3}, [%4];" \
                 : "=r"(r0), "=r"(r1), "=r"(r2), "=r"(r3) : "r"(a))

#define MMA_F16(c0, c1, c2, c3, a0, a1, a2, a3, b0, b1)                        \
    asm volatile("mma.sync.aligned.m16n8k16.row.col.f32.f16.f16.f32 "          \
                 "{%0,%1,%2,%3}, {%4,%5,%6,%7}, {%8,%9}, {%0,%1,%2,%3};"       \
                 : "+f"(c0), "+f"(c1), "+f"(c2), "+f"(c3)                      \
                 : "r"(a0), "r"(a1), "r"(a2), "r"(a3), "r"(b0), "r"(b1))

// ---------------------------------------------------------------------------
// Fused distance GEMM on fp16 tensor cores with cp.async + ldmatrix.
//   C[m][n] = xsq[m] + psq[n] - 2 * sum_k A16[m][k] * B16[n][k]
// Smem layout per tile: row r (128 B), 16B unit u stored at u ^ (r & 7).
// ---------------------------------------------------------------------------
__global__ __launch_bounds__(NTH, 2)
void dist_f16_v2_kernel(float* __restrict__ C) {
    extern __shared__ __align__(16) char smem[];
    uint32_t sb0;
    asm("{ .reg .u64 t; cvta.to.shared.u64 t, %1; cvt.u32.u64 %0, t; }"
        : "=r"(sb0) : "l"(smem));
    const uint32_t sb = (sb0 + 127u) & ~127u;

    const int tid  = threadIdx.x;
    const int lane = tid & 31;
    const int warp = tid >> 5;
    const int wm   = warp & 3;       // 4 warps along M -> 32 rows
    const int wn   = warp >> 2;      // 2 warps along N -> 64 cols
    const int bx   = blockIdx.x;     // N tile (0..3)
    const int by   = blockIdx.y;     // M tile (0..127)

    const __half* Ablk = g_a16 + (size_t)by * BM * D_;
    const __half* Bblk = g_b16 + (size_t)bx * BN * D_;

    // loader: 1024 16B units per operand per stage; 4 A + 4 B per thread
    const int lrow = tid >> 3;       // base row 0..31 (j adds 32)
    const int lu   = tid & 7;
    const uint32_t lsw = (uint32_t)((lu ^ (lrow & 7)) << 4);

    auto load_stage = [&](int s) {
        const uint32_t ab = sb + (uint32_t)(s % STAGES) * STAGEB;
        const uint32_t bb = ab + TILEB;
        const int kf = s * BKH + lu * 8;
        #pragma unroll
        for (int j = 0; j < 4; j++) {
            const int row = lrow + j * 32;
            cp_async16(ab + (uint32_t)row * 128 + lsw,
                       Ablk + (size_t)row * D_ + kf);
            cp_async16(bb + (uint32_t)row * 128 + lsw,
                       Bblk + (size_t)row * D_ + kf);
        }
    };

    // ldmatrix per-lane row/unit components (row & 7 == lane & 7 everywhere)
    const int rA   = wm * 32 + (lane & 7) + ((lane >> 3) & 1) * 8;
    const int uA   = lane >> 4;                 // k-unit offset
    const int rB   = wn * 64 + (lane & 7) + (lane >> 4) * 8;
    const int uB   = (lane >> 3) & 1;
    const uint32_t swz = (uint32_t)(lane & 7);

    float c[2][8][4];
    #pragma unroll
    for (int i = 0; i < 2; i++)
        #pragma unroll
        for (int j = 0; j < 8; j++)
            #pragma unroll
            for (int q = 0; q < 4; q++) c[i][j][q] = 0.f;

    load_stage(0); CP_COMMIT();
    load_stage(1); CP_COMMIT();

    for (int s = 0; s < NS; ++s) {
        if (s + 1 < NS) { CP_WAIT_1(); } else { CP_WAIT_0(); }
        __syncthreads();                        // stage s visible; buf(s+2) free
        if (s + 2 < NS) { load_stage(s + 2); CP_COMMIT(); }

        const uint32_t ab = sb + (uint32_t)(s % STAGES) * STAGEB;
        const uint32_t bb = ab + TILEB;

        #pragma unroll
        for (int kk = 0; kk < 4; kk++) {        // 4 x k16 per stage
            uint32_t a[2][4];
            #pragma unroll
            for (int i = 0; i < 2; i++) {
                const uint32_t addr = ab + (uint32_t)(rA + i * 16) * 128
                    + ((((uint32_t)(kk * 2 + uA)) ^ swz) << 4);
                LDSM_X4(a[i][0], a[i][1], a[i][2], a[i][3], addr);
            }
            #pragma unroll
            for (int jp = 0; jp < 4; jp++) {    // 2 n8 tiles per ldmatrix.x4
                uint32_t b0, b1, b2, b3;
                const uint32_t addr = bb + (uint32_t)(rB + jp * 16) * 128
                    + ((((uint32_t)(kk * 2 + uB)) ^ swz) << 4);
                LDSM_X4(b0, b1, b2, b3, addr);
                #pragma unroll
                for (int i = 0; i < 2; i++) {
                    MMA_F16(c[i][jp * 2][0], c[i][jp * 2][1],
                            c[i][jp * 2][2], c[i][jp * 2][3],
                            a[i][0], a[i][1], a[i][2], a[i][3], b0, b1);
                    MMA_F16(c[i][jp * 2 + 1][0], c[i][jp * 2 + 1][1],
                            c[i][jp * 2 + 1][2], c[i][jp * 2 + 1][3],
                            a[i][0], a[i][1], a[i][2], a[i][3], b2, b3);
                }
            }
        }
    }

    // ---- epilogue: dist = xsq + psq - 2*cross ----
    const int g = lane >> 2;
    const int t = lane & 3;
    #pragma unroll
    for (int i = 0; i < 2; i++) {
        const int mg0 = by * BM + wm * 32 + i * 16 + g;
        const float x0 = g_xsq[mg0];
        const float x1 = g_xsq[mg0 + 8];
        float* row0 = C + (size_t)mg0 * P_;
        float* row1 = C + (size_t)(mg0 + 8) * P_;
        #pragma unroll
        for (int j = 0; j < 8; j++) {
            const int ng = bx * BN + wn * 64 + j * 8 + 2 * t;
            const float p0 = g_psq[ng];
            const float p1 = g_psq[ng + 1];
            float2 v0, v1;
            v0.x = x0 + p0 - 2.f * c[i][j][0];
            v0.y = x0 + p1 - 2.f * c[i][j][1];
            v1.x = x1 + p0 - 2.f * c[i][j][2];
            v1.y = x1 + p1 - 2.f * c[i][j][3];
            *reinterpret_cast<float2*>(row0 + ng) = v0;
            *reinterpret_cast<float2*>(row1 + ng) = v1;
        }
    }
}

// ---------------------------------------------------------------------------
extern "C" void kernel_launch(void* const* d_in, const int* in_sizes, int n_in,
                              void* d_out, int out_size) {
    const float* inputs = (const float*)d_in[0];   // [M_, D_]
    const float* protos = (const float*)d_in[1];   // [P_, D_]
    float* out = (float*)d_out;

    // 1) fp16 copies + exact f32 norms (single pass over inputs)
    prep_kernel<<<(M_ + P_) / 16, 256>>>(inputs, protos);

    // 2) fused distance GEMM
    cudaFuncSetAttribute(dist_f16_v2_kernel,
                         cudaFuncAttributeMaxDynamicSharedMemorySize, SMEM_BYTES);
    dim3 grid(P_ / BN, M_ / BM);   // (4, 128)
    dist_f16_v2_kernel<<<grid, NTH, SMEM_BYTES>>>(out);

    // 3) second tuple output: prototypes passed through unchanged
    cudaMemcpyAsync(out + (size_t)M_ * P_, protos,
                    (size_t)P_ * D_ * sizeof(float),
                    cudaMemcpyDeviceToDevice);
}